// round 2
// baseline (speedup 1.0000x reference)
#include <cuda_runtime.h>

// Problem constants (fixed by the dataset)
#define NN  100000
#define EE  1600000
#define FIN 256
#define HD  128
#define CD  64

// ---------------- scratch (device globals; no allocation allowed) ----------
__device__ float d_deg[NN];
__device__ float d_dinv[NN];
__device__ int   d_cnt[NN];
__device__ int   d_rowstart[NN + 1];
__device__ int   d_cursor[NN];
__device__ int   d_eperm[EE];
__device__ float d_h1[(size_t)NN * HD];   // x @ W1
__device__ float d_a1[(size_t)NN * HD];   // relu(aggregate(h1) + b1)
__device__ float d_h2[(size_t)NN * CD];   // a1 @ W2

// ---------------- init ------------------------------------------------------
__global__ void k_init() {
    int i = blockIdx.x * blockDim.x + threadIdx.x;
    if (i < NN) {
        d_deg[i] = 1.0f;   // self-loop weight
        d_cnt[i] = 0;
    }
}

// ---------------- degree + in-edge count ------------------------------------
__global__ void k_deg_count(const int* __restrict__ dst,
                            const float* __restrict__ ew) {
    for (int e = blockIdx.x * blockDim.x + threadIdx.x; e < EE;
         e += gridDim.x * blockDim.x) {
        int d = dst[e];
        atomicAdd(&d_deg[d], ew[e]);
        atomicAdd(&d_cnt[d], 1);
    }
}

__global__ void k_dinv() {
    int i = blockIdx.x * blockDim.x + threadIdx.x;
    if (i < NN) d_dinv[i] = rsqrtf(d_deg[i]);  // deg >= 1 always (self-loop)
}

// ---------------- single-block exclusive scan over d_cnt --------------------
__global__ void k_exscan() {
    const int tid  = threadIdx.x;
    const int lane = tid & 31;
    const int wid  = tid >> 5;
    const int NW   = blockDim.x >> 5;
    __shared__ int wsum[32];
    __shared__ int running;
    if (tid == 0) running = 0;
    __syncthreads();
    for (int base = 0; base < NN; base += blockDim.x) {
        int i = base + tid;
        int v = (i < NN) ? d_cnt[i] : 0;
        int x = v;
        #pragma unroll
        for (int o = 1; o < 32; o <<= 1) {
            int y = __shfl_up_sync(0xffffffffu, x, o);
            if (lane >= o) x += y;
        }
        if (lane == 31) wsum[wid] = x;
        __syncthreads();
        if (wid == 0) {
            int s = (lane < NW) ? wsum[lane] : 0;
            #pragma unroll
            for (int o = 1; o < 32; o <<= 1) {
                int y = __shfl_up_sync(0xffffffffu, s, o);
                if (lane >= o) s += y;
            }
            wsum[lane] = s;
        }
        __syncthreads();
        int blockOffset = (wid > 0) ? wsum[wid - 1] : 0;
        int excl = running + blockOffset + x - v;
        if (i < NN) d_rowstart[i] = excl;
        __syncthreads();
        if (tid == blockDim.x - 1) running += wsum[NW - 1];
        __syncthreads();
    }
    if (tid == 0) d_rowstart[NN] = running;
}

__global__ void k_copy_cursor() {
    int i = blockIdx.x * blockDim.x + threadIdx.x;
    if (i < NN) d_cursor[i] = d_rowstart[i];
}

__global__ void k_scatter(const int* __restrict__ dst) {
    for (int e = blockIdx.x * blockDim.x + threadIdx.x; e < EE;
         e += gridDim.x * blockDim.x) {
        int d   = dst[e];
        int pos = atomicAdd(&d_cursor[d], 1);
        d_eperm[pos] = e;
    }
}

// ---------------- tiled SGEMM: C[M,N] = A[M,K] @ B[K,N] ---------------------
template <int BM, int BN, int BK, int TM, int TN>
__global__ void k_sgemm(const float* __restrict__ A,
                        const float* __restrict__ B,
                        float* __restrict__ C, int M, int N, int K) {
    __shared__ float As[BK][BM];
    __shared__ float Bs[BK][BN];
    constexpr int THREADS = (BM / TM) * (BN / TN);
    const int tid  = threadIdx.x;
    const int tcol = tid % (BN / TN);
    const int trow = tid / (BN / TN);
    const int rowBase = blockIdx.y * BM;
    const int colBase = blockIdx.x * BN;

    float acc[TM][TN];
    #pragma unroll
    for (int i = 0; i < TM; i++)
        #pragma unroll
        for (int j = 0; j < TN; j++) acc[i][j] = 0.0f;

    for (int k0 = 0; k0 < K; k0 += BK) {
        #pragma unroll
        for (int i = tid; i < BM * BK; i += THREADS) {
            int m  = i / BK;
            int kk = i % BK;
            int gr = rowBase + m;
            As[kk][m] = (gr < M) ? A[(size_t)gr * K + k0 + kk] : 0.0f;
        }
        #pragma unroll
        for (int i = tid; i < BK * BN; i += THREADS) {
            int kk = i / BN;
            int c  = i % BN;
            Bs[kk][c] = B[(size_t)(k0 + kk) * N + colBase + c];
        }
        __syncthreads();
        #pragma unroll
        for (int kk = 0; kk < BK; ++kk) {
            float ar[TM], br[TN];
            #pragma unroll
            for (int i = 0; i < TM; i++) ar[i] = As[kk][trow * TM + i];
            #pragma unroll
            for (int j = 0; j < TN; j++) br[j] = Bs[kk][tcol * TN + j];
            #pragma unroll
            for (int i = 0; i < TM; i++)
                #pragma unroll
                for (int j = 0; j < TN; j++) acc[i][j] += ar[i] * br[j];
        }
        __syncthreads();
    }
    #pragma unroll
    for (int i = 0; i < TM; i++) {
        int gr = rowBase + trow * TM + i;
        if (gr < M) {
            #pragma unroll
            for (int j = 0; j < TN; j++)
                C[(size_t)gr * N + colBase + tcol * TN + j] = acc[i][j];
        }
    }
}

// ---------------- pull-style aggregation: one warp per dst node -------------
template <int COLS, bool RELU>
__global__ void k_aggregate(const float* __restrict__ h,
                            const int* __restrict__ src,
                            const float* __restrict__ ew,
                            const float* __restrict__ bias,
                            float* __restrict__ out) {
    int gw   = (blockIdx.x * blockDim.x + threadIdx.x) >> 5;
    int lane = threadIdx.x & 31;
    if (gw >= NN) return;
    constexpr int V = COLS / 32;
    float di    = d_dinv[gw];
    float selfn = di * di;
    const float* hrow = h + (size_t)gw * COLS;
    float acc[V];
    #pragma unroll
    for (int v = 0; v < V; v++) acc[v] = selfn * hrow[lane + 32 * v];

    int beg = d_rowstart[gw];
    int end = d_rowstart[gw + 1];
    for (int p = beg; p < end; p++) {
        int e = d_eperm[p];
        int s = src[e];
        float nm = d_dinv[s] * ew[e] * di;
        const float* hs = h + (size_t)s * COLS;
        #pragma unroll
        for (int v = 0; v < V; v++) acc[v] += nm * hs[lane + 32 * v];
    }
    float* orow = out + (size_t)gw * COLS;
    #pragma unroll
    for (int v = 0; v < V; v++) {
        float val = acc[v] + bias[lane + 32 * v];
        if (RELU) val = fmaxf(val, 0.0f);
        orow[lane + 32 * v] = val;
    }
}

// ---------------- log_softmax over 64 classes, one warp per row -------------
__global__ void k_logsoftmax(float* __restrict__ out) {
    int gw   = (blockIdx.x * blockDim.x + threadIdx.x) >> 5;
    int lane = threadIdx.x & 31;
    if (gw >= NN) return;
    float* r = out + (size_t)gw * CD;
    float v0 = r[lane];
    float v1 = r[lane + 32];
    float m = fmaxf(v0, v1);
    #pragma unroll
    for (int o = 16; o; o >>= 1) m = fmaxf(m, __shfl_xor_sync(0xffffffffu, m, o));
    float s = expf(v0 - m) + expf(v1 - m);
    #pragma unroll
    for (int o = 16; o; o >>= 1) s += __shfl_xor_sync(0xffffffffu, s, o);
    float l = m + logf(s);
    r[lane]      = v0 - l;
    r[lane + 32] = v1 - l;
}

// ---------------- launch -----------------------------------------------------
extern "C" void kernel_launch(void* const* d_in, const int* in_sizes, int n_in,
                              void* d_out, int out_size) {
    const float* x  = (const float*)d_in[0];
    const int*   ei = (const int*)d_in[1];    // int32! (JAX demotes int64)
    const float* ew = (const float*)d_in[2];
    const float* W1 = (const float*)d_in[3];
    const float* b1 = (const float*)d_in[4];
    const float* W2 = (const float*)d_in[5];
    const float* b2 = (const float*)d_in[6];
    float* out = (float*)d_out;

    const int* src = ei;        // edge_index[0]
    const int* dst = ei + EE;   // edge_index[1]

    const int TB = 256;
    const int nodeBlocks = (NN + TB - 1) / TB;
    const int warpBlocks = (NN * 32 + TB - 1) / TB;

    // CSR build + normalization
    k_init<<<nodeBlocks, TB>>>();
    k_deg_count<<<2048, TB>>>(dst, ew);
    k_dinv<<<nodeBlocks, TB>>>();
    k_exscan<<<1, 1024>>>();
    k_copy_cursor<<<nodeBlocks, TB>>>();
    k_scatter<<<2048, TB>>>(dst);

    // Layer 1: h1 = x @ W1 ; a1 = relu(agg(h1) + b1)
    k_sgemm<128, 128, 16, 8, 8><<<dim3(1, (NN + 127) / 128), 256>>>(
        x, W1, d_h1, NN, HD, FIN);
    k_aggregate<HD, true><<<warpBlocks, TB>>>(d_h1, src, ew, b1, d_a1);

    // Layer 2: h2 = a1 @ W2 ; out = agg(h2) + b2
    k_sgemm<128, 64, 16, 8, 4><<<dim3(1, (NN + 127) / 128), 256>>>(
        d_a1, W2, d_h2, NN, CD, HD);
    k_aggregate<CD, false><<<warpBlocks, TB>>>(d_h2, src, ew, b2, out);

    // log_softmax in place on d_out
    k_logsoftmax<<<warpBlocks, TB>>>(out);
}

// round 3
// speedup vs baseline: 1.1879x; 1.1879x over previous
#include <cuda_runtime.h>

#define NN   100000
#define EE   1600000
#define FIN  256
#define HD   128
#define CD   64
#define SCAN_TB 256
#define NBLK ((NN + SCAN_TB - 1) / SCAN_TB)   // 391

// ---------------- scratch ----------------------------------------------------
__device__ float d_deg[NN];
__device__ float d_dinv[NN];
__device__ int   d_cnt[NN];
__device__ int   d_rowstart[NN + 1];
__device__ int   d_cursor[NN];
__device__ int   d_bsum[NBLK];
__device__ int   d_boff[NBLK];
__device__ int   d_esrc[EE];
__device__ float d_enorm[EE];
__device__ float d_h1[(size_t)NN * HD];
__device__ float d_a1[(size_t)NN * HD];
__device__ float d_h2[(size_t)NN * CD];

// ---------------- init + degree ---------------------------------------------
__global__ void k_init() {
    int i = blockIdx.x * blockDim.x + threadIdx.x;
    if (i < NN) { d_deg[i] = 1.0f; d_cnt[i] = 0; }
}

__global__ void k_deg_count(const int* __restrict__ dst,
                            const float* __restrict__ ew) {
    for (int e = blockIdx.x * blockDim.x + threadIdx.x; e < EE;
         e += gridDim.x * blockDim.x) {
        int d = dst[e];
        atomicAdd(&d_deg[d], ew[e]);
        atomicAdd(&d_cnt[d], 1);
    }
}

__global__ void k_dinv() {
    int i = blockIdx.x * blockDim.x + threadIdx.x;
    if (i < NN) d_dinv[i] = rsqrtf(d_deg[i]);
}

// ---------------- multi-block exclusive scan of d_cnt -----------------------
__global__ void k_scan_block() {            // grid NBLK, block 256
    __shared__ int ws[8];
    int tid = threadIdx.x, lane = tid & 31, wid = tid >> 5;
    int i = blockIdx.x * SCAN_TB + tid;
    int v = (i < NN) ? d_cnt[i] : 0;
    #pragma unroll
    for (int o = 16; o; o >>= 1) v += __shfl_xor_sync(0xffffffffu, v, o);
    if (lane == 0) ws[wid] = v;
    __syncthreads();
    if (tid == 0) {
        int t = 0;
        #pragma unroll
        for (int w = 0; w < 8; w++) t += ws[w];
        d_bsum[blockIdx.x] = t;
    }
}

__global__ void k_scan_top() {              // 1 block, 512 threads (NBLK<=512)
    __shared__ int ws[16];
    int tid = threadIdx.x, lane = tid & 31, wid = tid >> 5;
    int v = (tid < NBLK) ? d_bsum[tid] : 0;
    int x = v;
    #pragma unroll
    for (int o = 1; o < 32; o <<= 1) {
        int y = __shfl_up_sync(0xffffffffu, x, o);
        if (lane >= o) x += y;
    }
    if (lane == 31) ws[wid] = x;
    __syncthreads();
    if (wid == 0) {
        int s = (lane < 16) ? ws[lane] : 0;
        #pragma unroll
        for (int o = 1; o < 16; o <<= 1) {
            int y = __shfl_up_sync(0xffffffffu, s, o);
            if (lane >= o) s += y;
        }
        if (lane < 16) ws[lane] = s;
    }
    __syncthreads();
    int off = wid ? ws[wid - 1] : 0;
    if (tid < NBLK) d_boff[tid] = off + x - v;
    if (tid == 0) d_rowstart[NN] = EE;
}

__global__ void k_scan_apply() {            // grid NBLK, block 256
    __shared__ int ws[8];
    int tid = threadIdx.x, lane = tid & 31, wid = tid >> 5;
    int i = blockIdx.x * SCAN_TB + tid;
    int v = (i < NN) ? d_cnt[i] : 0;
    int x = v;
    #pragma unroll
    for (int o = 1; o < 32; o <<= 1) {
        int y = __shfl_up_sync(0xffffffffu, x, o);
        if (lane >= o) x += y;
    }
    if (lane == 31) ws[wid] = x;
    __syncthreads();
    if (wid == 0) {
        int s = (lane < 8) ? ws[lane] : 0;
        #pragma unroll
        for (int o = 1; o < 8; o <<= 1) {
            int y = __shfl_up_sync(0xffffffffu, s, o);
            if (lane >= o) s += y;
        }
        if (lane < 8) ws[lane] = s;
    }
    __syncthreads();
    int excl = x - v + (wid ? ws[wid - 1] : 0) + d_boff[blockIdx.x];
    if (i < NN) { d_rowstart[i] = excl; d_cursor[i] = excl; }
}

// ---------------- scatter: build fused edge records --------------------------
__global__ void k_scatter(const int* __restrict__ src,
                          const int* __restrict__ dst,
                          const float* __restrict__ ew) {
    for (int e = blockIdx.x * blockDim.x + threadIdx.x; e < EE;
         e += gridDim.x * blockDim.x) {
        int s = src[e], d = dst[e];
        int pos = atomicAdd(&d_cursor[d], 1);
        d_esrc[pos]  = s;
        d_enorm[pos] = d_dinv[s] * ew[e] * d_dinv[d];
    }
}

// ---------------- tiled SGEMM (float4, padded smem) --------------------------
template <int BM, int BN, int BK, int TM, int TN>
__global__ void k_sgemm(const float* __restrict__ A,
                        const float* __restrict__ B,
                        float* __restrict__ C, int M, int N, int K) {
    __shared__ float As[BK][BM + 1];
    __shared__ float Bs[BK][BN];
    constexpr int THREADS = (BM / TM) * (BN / TN);  // 256
    const int tid  = threadIdx.x;
    const int tcol = tid % (BN / TN);
    const int trow = tid / (BN / TN);
    const int rowBase = blockIdx.y * BM;
    const int colBase = blockIdx.x * BN;

    float acc[TM][TN];
    #pragma unroll
    for (int i = 0; i < TM; i++)
        #pragma unroll
        for (int j = 0; j < TN; j++) acc[i][j] = 0.0f;

    for (int k0 = 0; k0 < K; k0 += BK) {
        // A tile: BM*BK/4 float4s
        #pragma unroll
        for (int j = 0; j < (BM * BK) / (4 * THREADS); j++) {
            int f  = tid + j * THREADS;
            int m  = f / (BK / 4);
            int kv = f % (BK / 4);
            int gr = rowBase + m;
            float4 av = make_float4(0.f, 0.f, 0.f, 0.f);
            if (gr < M)
                av = *(const float4*)&A[(size_t)gr * K + k0 + kv * 4];
            As[kv * 4 + 0][m] = av.x;
            As[kv * 4 + 1][m] = av.y;
            As[kv * 4 + 2][m] = av.z;
            As[kv * 4 + 3][m] = av.w;
        }
        // B tile: BK*BN/4 float4s
        #pragma unroll
        for (int j = 0; j < (BK * BN) / (4 * THREADS); j++) {
            int f  = tid + j * THREADS;
            int kk = f / (BN / 4);
            int c4 = f % (BN / 4);
            *(float4*)&Bs[kk][c4 * 4] =
                *(const float4*)&B[(size_t)(k0 + kk) * N + colBase + c4 * 4];
        }
        __syncthreads();
        #pragma unroll
        for (int kk = 0; kk < BK; ++kk) {
            float ar[TM], br[TN];
            #pragma unroll
            for (int i = 0; i < TM; i++) ar[i] = As[kk][trow * TM + i];
            #pragma unroll
            for (int j4 = 0; j4 < TN / 4; j4++) {
                float4 bv = *(const float4*)&Bs[kk][tcol * TN + j4 * 4];
                br[j4 * 4 + 0] = bv.x; br[j4 * 4 + 1] = bv.y;
                br[j4 * 4 + 2] = bv.z; br[j4 * 4 + 3] = bv.w;
            }
            #pragma unroll
            for (int i = 0; i < TM; i++)
                #pragma unroll
                for (int j = 0; j < TN; j++) acc[i][j] += ar[i] * br[j];
        }
        __syncthreads();
    }
    #pragma unroll
    for (int i = 0; i < TM; i++) {
        int gr = rowBase + trow * TM + i;
        if (gr < M) {
            #pragma unroll
            for (int j4 = 0; j4 < TN / 4; j4++) {
                float4 cv = make_float4(acc[i][j4 * 4 + 0], acc[i][j4 * 4 + 1],
                                        acc[i][j4 * 4 + 2], acc[i][j4 * 4 + 3]);
                *(float4*)&C[(size_t)gr * N + colBase + tcol * TN + j4 * 4] = cv;
            }
        }
    }
}

// ---------------- aggregation: warp per node, fused edge records -------------
__global__ void k_agg128(const float* __restrict__ h,
                         const float* __restrict__ bias,
                         float* __restrict__ out) {
    int gw   = (blockIdx.x * blockDim.x + threadIdx.x) >> 5;
    int lane = threadIdx.x & 31;
    if (gw >= NN) return;
    float di = d_dinv[gw];
    float s0 = di * di;
    float4 hv = ((const float4*)(h + (size_t)gw * HD))[lane];
    float4 acc = make_float4(s0 * hv.x, s0 * hv.y, s0 * hv.z, s0 * hv.w);

    int p   = d_rowstart[gw];
    int end = d_rowstart[gw + 1];
    for (; p + 3 < end; p += 4) {
        int   sA = d_esrc[p],     sB = d_esrc[p + 1];
        int   sC = d_esrc[p + 2], sD = d_esrc[p + 3];
        float nA = d_enorm[p],     nB = d_enorm[p + 1];
        float nC = d_enorm[p + 2], nD = d_enorm[p + 3];
        float4 a = ((const float4*)(h + (size_t)sA * HD))[lane];
        float4 b = ((const float4*)(h + (size_t)sB * HD))[lane];
        float4 c = ((const float4*)(h + (size_t)sC * HD))[lane];
        float4 d = ((const float4*)(h + (size_t)sD * HD))[lane];
        acc.x += nA * a.x + nB * b.x + nC * c.x + nD * d.x;
        acc.y += nA * a.y + nB * b.y + nC * c.y + nD * d.y;
        acc.z += nA * a.z + nB * b.z + nC * c.z + nD * d.z;
        acc.w += nA * a.w + nB * b.w + nC * c.w + nD * d.w;
    }
    for (; p < end; p++) {
        int   s = d_esrc[p];
        float n = d_enorm[p];
        float4 a = ((const float4*)(h + (size_t)s * HD))[lane];
        acc.x += n * a.x; acc.y += n * a.y; acc.z += n * a.z; acc.w += n * a.w;
    }
    float4 bv = ((const float4*)bias)[lane];
    acc.x = fmaxf(acc.x + bv.x, 0.0f);
    acc.y = fmaxf(acc.y + bv.y, 0.0f);
    acc.z = fmaxf(acc.z + bv.z, 0.0f);
    acc.w = fmaxf(acc.w + bv.w, 0.0f);
    ((float4*)(out + (size_t)gw * HD))[lane] = acc;
}

__global__ void k_agg64(const float* __restrict__ h,
                        const float* __restrict__ bias,
                        float* __restrict__ out) {
    int gw   = (blockIdx.x * blockDim.x + threadIdx.x) >> 5;
    int lane = threadIdx.x & 31;
    if (gw >= NN) return;
    float di = d_dinv[gw];
    float s0 = di * di;
    float2 hv = ((const float2*)(h + (size_t)gw * CD))[lane];
    float2 acc = make_float2(s0 * hv.x, s0 * hv.y);

    int p   = d_rowstart[gw];
    int end = d_rowstart[gw + 1];
    for (; p + 3 < end; p += 4) {
        int   sA = d_esrc[p],     sB = d_esrc[p + 1];
        int   sC = d_esrc[p + 2], sD = d_esrc[p + 3];
        float nA = d_enorm[p],     nB = d_enorm[p + 1];
        float nC = d_enorm[p + 2], nD = d_enorm[p + 3];
        float2 a = ((const float2*)(h + (size_t)sA * CD))[lane];
        float2 b = ((const float2*)(h + (size_t)sB * CD))[lane];
        float2 c = ((const float2*)(h + (size_t)sC * CD))[lane];
        float2 d = ((const float2*)(h + (size_t)sD * CD))[lane];
        acc.x += nA * a.x + nB * b.x + nC * c.x + nD * d.x;
        acc.y += nA * a.y + nB * b.y + nC * c.y + nD * d.y;
    }
    for (; p < end; p++) {
        int   s = d_esrc[p];
        float n = d_enorm[p];
        float2 a = ((const float2*)(h + (size_t)s * CD))[lane];
        acc.x += n * a.x; acc.y += n * a.y;
    }
    float2 bv = ((const float2*)bias)[lane];
    acc.x += bv.x; acc.y += bv.y;
    ((float2*)(out + (size_t)gw * CD))[lane] = acc;
}

// ---------------- log_softmax over 64 classes --------------------------------
__global__ void k_logsoftmax(float* __restrict__ out) {
    int gw   = (blockIdx.x * blockDim.x + threadIdx.x) >> 5;
    int lane = threadIdx.x & 31;
    if (gw >= NN) return;
    float* r = out + (size_t)gw * CD;
    float v0 = r[lane];
    float v1 = r[lane + 32];
    float m = fmaxf(v0, v1);
    #pragma unroll
    for (int o = 16; o; o >>= 1) m = fmaxf(m, __shfl_xor_sync(0xffffffffu, m, o));
    float s = expf(v0 - m) + expf(v1 - m);
    #pragma unroll
    for (int o = 16; o; o >>= 1) s += __shfl_xor_sync(0xffffffffu, s, o);
    float l = m + logf(s);
    r[lane]      = v0 - l;
    r[lane + 32] = v1 - l;
}

// ---------------- launch ------------------------------------------------------
extern "C" void kernel_launch(void* const* d_in, const int* in_sizes, int n_in,
                              void* d_out, int out_size) {
    const float* x  = (const float*)d_in[0];
    const int*   ei = (const int*)d_in[1];    // int32 (JAX default demotion)
    const float* ew = (const float*)d_in[2];
    const float* W1 = (const float*)d_in[3];
    const float* b1 = (const float*)d_in[4];
    const float* W2 = (const float*)d_in[5];
    const float* b2 = (const float*)d_in[6];
    float* out = (float*)d_out;

    const int* src = ei;
    const int* dst = ei + EE;

    const int TB = 256;
    const int nodeBlocks = (NN + TB - 1) / TB;
    const int warpBlocks = (NN * 32 + TB - 1) / TB;

    // 1-3: degree / normalization prep
    k_init<<<nodeBlocks, TB>>>();
    k_deg_count<<<2048, TB>>>(dst, ew);
    k_dinv<<<nodeBlocks, TB>>>();

    // 4: GEMM1 (placed here to land in ncu capture window; independent of CSR)
    k_sgemm<128, 128, 16, 8, 8><<<dim3(1, (NN + 127) / 128), 256>>>(
        x, W1, d_h1, NN, HD, FIN);

    // 5-8: CSR build
    k_scan_block<<<NBLK, SCAN_TB>>>();
    k_scan_top<<<1, 512>>>();
    k_scan_apply<<<NBLK, SCAN_TB>>>();
    k_scatter<<<2048, TB>>>(src, dst, ew);

    // 9: aggregate layer 1 (+bias +relu)
    k_agg128<<<warpBlocks, TB>>>(d_h1, b1, d_a1);

    // 10: GEMM2
    k_sgemm<128, 64, 16, 8, 4><<<dim3(1, (NN + 127) / 128), 256>>>(
        d_a1, W2, d_h2, NN, CD, HD);

    // 11: aggregate layer 2 (+bias)
    k_agg64<<<warpBlocks, TB>>>(d_h2, b2, out);

    // 12: log_softmax in place
    k_logsoftmax<<<warpBlocks, TB>>>(out);
}

// round 4
// speedup vs baseline: 1.3610x; 1.1457x over previous
#include <cuda_runtime.h>

#define NN   100000
#define EE   1600000
#define FIN  256
#define HD   128
#define CD   64
#define SCAN_TB 256
#define NBLK ((NN + SCAN_TB - 1) / SCAN_TB)   // 391

// ---------------- scratch ----------------------------------------------------
__device__ float d_deg[NN];
__device__ float d_dinv[NN];
__device__ int   d_cnt[NN];
__device__ int   d_rowstart[NN + 1];
__device__ int   d_cursor[NN];
__device__ unsigned int d_scanstate[NBLK];
__device__ unsigned long long d_rec[EE];      // packed (src:int low32, norm:float high32)
__device__ float d_h1[(size_t)NN * HD];
__device__ float d_a1[(size_t)NN * HD];
__device__ float d_h2[(size_t)NN * CD];

// ---------------- 1: init -----------------------------------------------------
__global__ void k_init() {
    int i = blockIdx.x * blockDim.x + threadIdx.x;
    if (i < NN) { d_deg[i] = 1.0f; d_cnt[i] = 0; }
    if (i < NBLK) d_scanstate[i] = 0u;
}

// ---------------- 2: degree + in-edge count -----------------------------------
__global__ void k_deg_count(const int* __restrict__ dst,
                            const float* __restrict__ ew) {
    for (int e = blockIdx.x * blockDim.x + threadIdx.x; e < EE;
         e += gridDim.x * blockDim.x) {
        int d = dst[e];
        atomicAdd(&d_deg[d], ew[e]);
        atomicAdd(&d_cnt[d], 1);
    }
}

// ---------------- 3: fused single-pass scan + dinv + cursor --------------------
// decoupled lookback; state word = tag<<30 | value  (tag 1=partial, 2=inclusive)
__global__ void k_scan_fused() {
    const int b   = blockIdx.x;
    const int tid = threadIdx.x;
    const int lane = tid & 31, wid = tid >> 5;
    __shared__ int ws[8];
    __shared__ int s_prev;

    int i = b * SCAN_TB + tid;
    int v = (i < NN) ? d_cnt[i] : 0;
    int x = v;
    #pragma unroll
    for (int o = 1; o < 32; o <<= 1) {
        int y = __shfl_up_sync(0xffffffffu, x, o);
        if (lane >= o) x += y;
    }
    if (lane == 31) ws[wid] = x;
    __syncthreads();
    if (wid == 0 && lane < 8) {
        int s = ws[lane];
        #pragma unroll
        for (int o = 1; o < 8; o <<= 1) {
            int y = __shfl_up_sync(0x000000ffu, s, o);
            if (lane >= o) s += y;
        }
        ws[lane] = s;
    }
    __syncthreads();
    int blockExcl = wid ? ws[wid - 1] : 0;
    int incl = blockExcl + x;            // inclusive within block
    int blockSum = ws[7];

    if (tid == 0) {
        if (b == 0) {
            __threadfence();
            atomicExch(&d_scanstate[0], (2u << 30) | (unsigned)blockSum);
            s_prev = 0;
        } else {
            atomicExch(&d_scanstate[b], (1u << 30) | (unsigned)blockSum);
            int run = 0;
            int j = b - 1;
            while (true) {
                unsigned st = atomicAdd(&d_scanstate[j], 0u);
                unsigned tag = st >> 30;
                if (tag == 0u) continue;       // not published yet
                run += (int)(st & 0x3FFFFFFFu);
                if (tag == 2u) break;
                j--;
            }
            __threadfence();
            atomicExch(&d_scanstate[b], (2u << 30) | (unsigned)(run + blockSum));
            s_prev = run;
        }
    }
    __syncthreads();
    int excl = s_prev + incl - v;
    if (i < NN) {
        d_rowstart[i] = excl;
        d_cursor[i]   = excl;
        d_dinv[i]     = rsqrtf(d_deg[i]);
    }
    if (i == NN - 1) d_rowstart[NN] = EE;
}

// ---------------- 4: scatter packed edge records (PROFILED SLOT) ---------------
__global__ void k_scatter(const int* __restrict__ src,
                          const int* __restrict__ dst,
                          const float* __restrict__ ew) {
    for (int e = blockIdx.x * blockDim.x + threadIdx.x; e < EE;
         e += gridDim.x * blockDim.x) {
        int s = src[e], d = dst[e];
        int pos = atomicAdd(&d_cursor[d], 1);
        float n = d_dinv[s] * ew[e] * d_dinv[d];
        unsigned long long packed =
            ((unsigned long long)__float_as_uint(n) << 32) | (unsigned)s;
        d_rec[pos] = packed;
    }
}

// ---------------- tiled SGEMM 128x64x16, TM8/TN4 (regs ~60, occ ~50%) ----------
template <int BM, int BN, int BK, int TM, int TN>
__global__ void k_sgemm(const float* __restrict__ A,
                        const float* __restrict__ B,
                        float* __restrict__ C, int M, int N, int K) {
    __shared__ float As[BK][BM + 1];
    __shared__ float Bs[BK][BN];
    constexpr int THREADS = (BM / TM) * (BN / TN);  // 256
    const int tid  = threadIdx.x;
    const int tcol = tid % (BN / TN);
    const int trow = tid / (BN / TN);
    const int rowBase = blockIdx.y * BM;
    const int colBase = blockIdx.x * BN;

    float acc[TM][TN];
    #pragma unroll
    for (int i = 0; i < TM; i++)
        #pragma unroll
        for (int j = 0; j < TN; j++) acc[i][j] = 0.0f;

    for (int k0 = 0; k0 < K; k0 += BK) {
        #pragma unroll
        for (int j = 0; j < (BM * BK) / (4 * THREADS); j++) {
            int f  = tid + j * THREADS;
            int m  = f / (BK / 4);
            int kv = f % (BK / 4);
            int gr = rowBase + m;
            float4 av = make_float4(0.f, 0.f, 0.f, 0.f);
            if (gr < M)
                av = *(const float4*)&A[(size_t)gr * K + k0 + kv * 4];
            As[kv * 4 + 0][m] = av.x;
            As[kv * 4 + 1][m] = av.y;
            As[kv * 4 + 2][m] = av.z;
            As[kv * 4 + 3][m] = av.w;
        }
        #pragma unroll
        for (int j = 0; j < (BK * BN) / (4 * THREADS); j++) {
            int f  = tid + j * THREADS;
            int kk = f / (BN / 4);
            int c4 = f % (BN / 4);
            *(float4*)&Bs[kk][c4 * 4] =
                *(const float4*)&B[(size_t)(k0 + kk) * N + colBase + c4 * 4];
        }
        __syncthreads();
        #pragma unroll
        for (int kk = 0; kk < BK; ++kk) {
            float ar[TM], br[TN];
            #pragma unroll
            for (int i = 0; i < TM; i++) ar[i] = As[kk][trow * TM + i];
            #pragma unroll
            for (int j4 = 0; j4 < TN / 4; j4++) {
                float4 bv = *(const float4*)&Bs[kk][tcol * TN + j4 * 4];
                br[j4 * 4 + 0] = bv.x; br[j4 * 4 + 1] = bv.y;
                br[j4 * 4 + 2] = bv.z; br[j4 * 4 + 3] = bv.w;
            }
            #pragma unroll
            for (int i = 0; i < TM; i++)
                #pragma unroll
                for (int j = 0; j < TN; j++) acc[i][j] += ar[i] * br[j];
        }
        __syncthreads();
    }
    #pragma unroll
    for (int i = 0; i < TM; i++) {
        int gr = rowBase + trow * TM + i;
        if (gr < M) {
            #pragma unroll
            for (int j4 = 0; j4 < TN / 4; j4++) {
                float4 cv = make_float4(acc[i][j4 * 4 + 0], acc[i][j4 * 4 + 1],
                                        acc[i][j4 * 4 + 2], acc[i][j4 * 4 + 3]);
                *(float4*)&C[(size_t)gr * N + colBase + tcol * TN + j4 * 4] = cv;
            }
        }
    }
}

// ---------------- aggregation L1: warp/node, 8-deep gather pipeline ------------
__global__ void k_agg128(const float* __restrict__ h,
                         const float* __restrict__ bias,
                         float* __restrict__ out) {
    int gw   = (blockIdx.x * blockDim.x + threadIdx.x) >> 5;
    int lane = threadIdx.x & 31;
    if (gw >= NN) return;
    float di = d_dinv[gw];
    float s0 = di * di;
    float4 hv = __ldg(&((const float4*)(h + (size_t)gw * HD))[lane]);
    float4 acc = make_float4(s0 * hv.x, s0 * hv.y, s0 * hv.z, s0 * hv.w);

    int p   = d_rowstart[gw];
    int end = d_rowstart[gw + 1];
    for (; p + 7 < end; p += 8) {
        unsigned long long r[8];
        #pragma unroll
        for (int q = 0; q < 8; q++) r[q] = __ldg(&d_rec[p + q]);
        float4 g[8];
        #pragma unroll
        for (int q = 0; q < 8; q++) {
            int s = (int)(unsigned)r[q];
            g[q] = __ldg(&((const float4*)(h + (size_t)s * HD))[lane]);
        }
        #pragma unroll
        for (int q = 0; q < 8; q++) {
            float n = __uint_as_float((unsigned)(r[q] >> 32));
            acc.x += n * g[q].x; acc.y += n * g[q].y;
            acc.z += n * g[q].z; acc.w += n * g[q].w;
        }
    }
    for (; p < end; p++) {
        unsigned long long rr = __ldg(&d_rec[p]);
        int   s = (int)(unsigned)rr;
        float n = __uint_as_float((unsigned)(rr >> 32));
        float4 a = __ldg(&((const float4*)(h + (size_t)s * HD))[lane]);
        acc.x += n * a.x; acc.y += n * a.y; acc.z += n * a.z; acc.w += n * a.w;
    }
    float4 bv = __ldg(&((const float4*)bias)[lane]);
    acc.x = fmaxf(acc.x + bv.x, 0.0f);
    acc.y = fmaxf(acc.y + bv.y, 0.0f);
    acc.z = fmaxf(acc.z + bv.z, 0.0f);
    acc.w = fmaxf(acc.w + bv.w, 0.0f);
    ((float4*)(out + (size_t)gw * HD))[lane] = acc;
}

// ---------------- aggregation L2 + bias + log_softmax fused --------------------
__global__ void k_agg64_sm(const float* __restrict__ h,
                           const float* __restrict__ bias,
                           float* __restrict__ out) {
    int gw   = (blockIdx.x * blockDim.x + threadIdx.x) >> 5;
    int lane = threadIdx.x & 31;
    if (gw >= NN) return;
    float di = d_dinv[gw];
    float s0 = di * di;
    float2 hv = __ldg(&((const float2*)(h + (size_t)gw * CD))[lane]);
    float2 acc = make_float2(s0 * hv.x, s0 * hv.y);

    int p   = d_rowstart[gw];
    int end = d_rowstart[gw + 1];
    for (; p + 7 < end; p += 8) {
        unsigned long long r[8];
        #pragma unroll
        for (int q = 0; q < 8; q++) r[q] = __ldg(&d_rec[p + q]);
        float2 g[8];
        #pragma unroll
        for (int q = 0; q < 8; q++) {
            int s = (int)(unsigned)r[q];
            g[q] = __ldg(&((const float2*)(h + (size_t)s * CD))[lane]);
        }
        #pragma unroll
        for (int q = 0; q < 8; q++) {
            float n = __uint_as_float((unsigned)(r[q] >> 32));
            acc.x += n * g[q].x; acc.y += n * g[q].y;
        }
    }
    for (; p < end; p++) {
        unsigned long long rr = __ldg(&d_rec[p]);
        int   s = (int)(unsigned)rr;
        float n = __uint_as_float((unsigned)(rr >> 32));
        float2 a = __ldg(&((const float2*)(h + (size_t)s * CD))[lane]);
        acc.x += n * a.x; acc.y += n * a.y;
    }
    float2 bv = __ldg(&((const float2*)bias)[lane]);
    acc.x += bv.x; acc.y += bv.y;

    // fused log_softmax over the 64 values held as (acc.x, acc.y) per lane
    float m = fmaxf(acc.x, acc.y);
    #pragma unroll
    for (int o = 16; o; o >>= 1) m = fmaxf(m, __shfl_xor_sync(0xffffffffu, m, o));
    float s = expf(acc.x - m) + expf(acc.y - m);
    #pragma unroll
    for (int o = 16; o; o >>= 1) s += __shfl_xor_sync(0xffffffffu, s, o);
    float l = m + logf(s);
    ((float2*)(out + (size_t)gw * CD))[lane] = make_float2(acc.x - l, acc.y - l);
}

// ---------------- launch --------------------------------------------------------
extern "C" void kernel_launch(void* const* d_in, const int* in_sizes, int n_in,
                              void* d_out, int out_size) {
    const float* x  = (const float*)d_in[0];
    const int*   ei = (const int*)d_in[1];    // int32 (JAX default demotion)
    const float* ew = (const float*)d_in[2];
    const float* W1 = (const float*)d_in[3];
    const float* b1 = (const float*)d_in[4];
    const float* W2 = (const float*)d_in[5];
    const float* b2 = (const float*)d_in[6];
    float* out = (float*)d_out;

    const int* src = ei;
    const int* dst = ei + EE;

    const int TB = 256;
    const int nodeBlocks = (NN + TB - 1) / TB;
    const int warpBlocks = (NN * 32 + TB - 1) / TB;

    k_init<<<nodeBlocks, TB>>>();                       // 1
    k_deg_count<<<2048, TB>>>(dst, ew);                 // 2
    k_scan_fused<<<NBLK, SCAN_TB>>>();                  // 3 (scan + dinv + cursor)
    k_scatter<<<2048, TB>>>(src, dst, ew);              // 4  <-- profiled slot

    k_sgemm<128, 64, 16, 8, 4><<<dim3(2, (NN + 127) / 128), 256>>>(
        x, W1, d_h1, NN, HD, FIN);                      // 5
    k_agg128<<<warpBlocks, TB>>>(d_h1, b1, d_a1);       // 6
    k_sgemm<128, 64, 16, 8, 4><<<dim3(1, (NN + 127) / 128), 256>>>(
        d_a1, W2, d_h2, NN, CD, HD);                    // 7
    k_agg64_sm<<<warpBlocks, TB>>>(d_h2, b2, out);      // 8
}